// round 3
// baseline (speedup 1.0000x reference)
#include <cuda_runtime.h>

#define NB    4
#define NPTS  8192
#define TPB   128
#define TQ    8
#define QB    (TPB*TQ)        // 1024 queries per block
#define MC    1024            // targets per block chunk
#define NPAIRS (NB*NPTS/2)    // 16384 target pairs

// Scratch (no allocations allowed):
__device__ float4   g_prepA[NB*NPTS];   // prepped array1 as targets (512 KB)
__device__ float4   g_prepB[NB*NPTS];   // prepped array2 as targets
__device__ unsigned g_enc1[NB*NPTS];    // encoded min(e) for dist1
__device__ unsigned g_enc2[NB*NPTS];    // encoded min(e) for dist2
__device__ float    g_part[128];

__device__ __forceinline__ unsigned long long pk2(float lo, float hi) {
    unsigned long long r;
    asm("mov.b64 %0, {%1,%2};" : "=l"(r) : "f"(lo), "f"(hi));
    return r;
}
// Order-preserving float->uint encoding (works for negatives) for atomicMin.
__device__ __forceinline__ unsigned fenc(float f) {
    unsigned b = __float_as_uint(f);
    return b ^ ((b & 0x80000000u) ? 0xFFFFFFFFu : 0x80000000u);
}
__device__ __forceinline__ float fdec(unsigned u) {
    unsigned b = (u & 0x80000000u) ? (u ^ 0x80000000u) : ~u;
    return __uint_as_float(b);
}

__global__ void init_kernel() {
    int i = blockIdx.x * blockDim.x + threadIdx.x;
    if (i < NB * NPTS) { g_enc1[i] = 0xFFFFFFFFu; g_enc2[i] = 0xFFFFFFFFu; }
}

// Pack targets pair-interleaved: for pair p (points 2p,2p+1 within batch):
//   dst[2p]   = (-x0,-x1,-y0,-y1)
//   dst[2p+1] = (-z0,-z1, h0, h1)   with h = 0.5*(x^2+y^2+z^2)
__global__ void prep_kernel(const float* __restrict__ src, int which) {
    float4* dst = which ? g_prepB : g_prepA;
    int p = blockIdx.x * blockDim.x + threadIdx.x;
    if (p >= NPAIRS) return;
    const float* s = src + p * 6;   // batch boundaries are pair-aligned
    float x0 = s[0], y0 = s[1], z0 = s[2];
    float x1 = s[3], y1 = s[4], z1 = s[5];
    float h0 = 0.5f * (x0*x0 + y0*y0 + z0*z0);
    float h1 = 0.5f * (x1*x1 + y1*y1 + z1*z1);
    dst[2*p    ] = make_float4(-x0, -x1, -y0, -y1);
    dst[2*p + 1] = make_float4(-z0, -z1,  h0,  h1);
}

// dir=0: queries=array1, targets=g_prepB(array2), out=g_enc1
// dir=1: queries=array2, targets=g_prepA(array1), out=g_enc2
__global__ __launch_bounds__(TPB) void pass_kernel(const float* __restrict__ qraw, int dir) {
    const float4* tp     = dir ? g_prepA : g_prepB;
    unsigned*     encOut = dir ? g_enc2  : g_enc1;

    int b  = blockIdx.z;
    int q0 = b * NPTS + blockIdx.x * QB;

    __shared__ float4 sh[MC];   // 16 KB: 512 target-pairs * 2 float4

    const float4* gsrc = tp + b * NPTS + blockIdx.y * MC;
    for (int i = threadIdx.x; i < MC; i += TPB) sh[i] = gsrc[i];

    unsigned long long X2[TQ], Y2[TQ], Z2[TQ];
    float mn[TQ];
#pragma unroll
    for (int k = 0; k < TQ; k++) {
        int qg = q0 + threadIdx.x + k * TPB;
        float x = qraw[3*qg], y = qraw[3*qg+1], z = qraw[3*qg+2];
        X2[k] = pk2(x, x); Y2[k] = pk2(y, y); Z2[k] = pk2(z, z);
        mn[k] = __int_as_float(0x7f800000);   // +inf
    }
    __syncthreads();

#pragma unroll 2
    for (int p = 0; p < MC / 2; ++p) {
        float4 A  = sh[2*p];
        float4 Bv = sh[2*p + 1];
        unsigned long long NX = pk2(A.x,  A.y);
        unsigned long long NY = pk2(A.z,  A.w);
        unsigned long long NZ = pk2(Bv.x, Bv.y);
        unsigned long long H  = pk2(Bv.z, Bv.w);
#pragma unroll
        for (int k = 0; k < TQ; k++) {
            float lo, hi;
            // e = h - (xq*xt + yq*yt + zq*zt), two targets per packed op
            asm("{\n\t.reg .b64 t;\n\t"
                "fma.rn.f32x2 t, %2, %3, %4;\n\t"
                "fma.rn.f32x2 t, %5, %6, t;\n\t"
                "fma.rn.f32x2 t, %7, %8, t;\n\t"
                "mov.b64 {%0,%1}, t;\n\t}"
                : "=f"(lo), "=f"(hi)
                : "l"(Z2[k]), "l"(NZ), "l"(H),
                  "l"(Y2[k]), "l"(NY),
                  "l"(X2[k]), "l"(NX));
            mn[k] = fminf(mn[k], fminf(lo, hi));
        }
    }

#pragma unroll
    for (int k = 0; k < TQ; k++)
        atomicMin(&encOut[q0 + threadIdx.x + k * TPB], fenc(mn[k]));
}

// Deterministic two-stage reduction: dist = a^2 + 2*e_min ; output = (sum1+sum2)/32768
__global__ void reduce1_kernel(const float* __restrict__ a1, const float* __restrict__ a2r) {
    __shared__ float ss[256];
    int blk = blockIdx.x;                       // 0..127
    const float*    raw = (blk & 64) ? a2r    : a1;
    const unsigned* enc = (blk & 64) ? g_enc2 : g_enc1;
    int base = (blk & 63) * 512;
    float s = 0.f;
    for (int i = threadIdx.x; i < 512; i += 256) {
        int idx = base + i;
        float x = raw[3*idx], y = raw[3*idx+1], z = raw[3*idx+2];
        s += (x*x + y*y + z*z) + 2.0f * fdec(enc[idx]);
    }
    ss[threadIdx.x] = s; __syncthreads();
    for (int o = 128; o > 0; o >>= 1) {
        if (threadIdx.x < o) ss[threadIdx.x] += ss[threadIdx.x + o];
        __syncthreads();
    }
    if (threadIdx.x == 0) g_part[blk] = ss[0];
}

__global__ void reduce2_kernel(float* __restrict__ out) {
    __shared__ float ss[128];
    ss[threadIdx.x] = g_part[threadIdx.x]; __syncthreads();
    for (int o = 64; o > 0; o >>= 1) {
        if (threadIdx.x < o) ss[threadIdx.x] += ss[threadIdx.x + o];
        __syncthreads();
    }
    // cd = mean_b( mean_n dist1 + mean_m dist2 ) = (sum1+sum2)/(B*N)
    if (threadIdx.x == 0) out[0] = ss[0] * (1.0f / (float)(NB * NPTS));
}

extern "C" void kernel_launch(void* const* d_in, const int* in_sizes, int n_in,
                              void* d_out, int out_size) {
    const float* a1 = (const float*)d_in[0];   // array1 [4,8192,3]
    const float* a2 = (const float*)d_in[1];   // array2 [4,8192,3]
    float* out = (float*)d_out;

    init_kernel<<<128, 256>>>();
    prep_kernel<<<NPAIRS / 256, 256>>>(a1, 0);  // -> g_prepA
    prep_kernel<<<NPAIRS / 256, 256>>>(a2, 1);  // -> g_prepB

    dim3 grid(NPTS / QB, NPTS / MC, NB);        // (8, 8, 4) = 256 blocks
    pass_kernel<<<grid, TPB>>>(a1, 0);          // dist1: a1 vs a2
    pass_kernel<<<grid, TPB>>>(a2, 1);          // dist2: a2 vs a1

    reduce1_kernel<<<128, 256>>>(a1, a2);
    reduce2_kernel<<<1, 128>>>(out);
}

// round 4
// speedup vs baseline: 1.4129x; 1.4129x over previous
#include <cuda_runtime.h>

#define NB    4
#define NPTS  8192
#define TPB   128
#define TQ    4
#define QB    (TPB*TQ)        // 512 queries per block
#define MC    512             // targets per block chunk
#define NPAIRS (NB*NPTS/2)    // 16384 target pairs

// Scratch (no allocations allowed):
__device__ float4   g_prepA[NB*NPTS];   // prepped array1 as targets (512 KB)
__device__ float4   g_prepB[NB*NPTS];   // prepped array2 as targets
__device__ unsigned g_enc1[NB*NPTS];    // encoded min(e) for dist1 (array1 queries)
__device__ unsigned g_enc2[NB*NPTS];    // encoded min(e) for dist2 (array2 queries)
__device__ float    g_part[128];

__device__ __forceinline__ unsigned long long pk2(float lo, float hi) {
    unsigned long long r;
    asm("mov.b64 %0, {%1,%2};" : "=l"(r) : "f"(lo), "f"(hi));
    return r;
}
// Order-preserving float->uint encoding (handles negatives) for atomicMin.
__device__ __forceinline__ unsigned fenc(float f) {
    unsigned b = __float_as_uint(f);
    return b ^ ((b & 0x80000000u) ? 0xFFFFFFFFu : 0x80000000u);
}
__device__ __forceinline__ float fdec(unsigned u) {
    unsigned b = (u & 0x80000000u) ? (u ^ 0x80000000u) : ~u;
    return __uint_as_float(b);
}

// Pack targets pair-interleaved AND init the matching enc array to +inf:
//   dst[2p]   = (-x0,-x1,-y0,-y1)
//   dst[2p+1] = (-z0,-z1, h0, h1)   with h = 0.5*(x^2+y^2+z^2)
__global__ void prep_kernel(const float* __restrict__ src, int which) {
    float4*   dst = which ? g_prepB : g_prepA;
    unsigned* enc = which ? g_enc2  : g_enc1;
    int p = blockIdx.x * blockDim.x + threadIdx.x;
    if (p >= NPAIRS) return;
    const float* s = src + p * 6;   // batch boundaries are pair-aligned
    float x0 = s[0], y0 = s[1], z0 = s[2];
    float x1 = s[3], y1 = s[4], z1 = s[5];
    float h0 = 0.5f * (x0*x0 + y0*y0 + z0*z0);
    float h1 = 0.5f * (x1*x1 + y1*y1 + z1*z1);
    dst[2*p    ] = make_float4(-x0, -x1, -y0, -y1);
    dst[2*p + 1] = make_float4(-z0, -z1,  h0,  h1);
    enc[2*p    ] = 0xFFFFFFFFu;
    enc[2*p + 1] = 0xFFFFFFFFu;
}

// Fused both directions: blockIdx.z encodes (batch, dir).
// dir=0: queries=array1, targets=g_prepB(array2), out=g_enc1
// dir=1: queries=array2, targets=g_prepA(array1), out=g_enc2
__global__ __launch_bounds__(TPB) void pass_kernel(const float* __restrict__ q1,
                                                   const float* __restrict__ q2) {
    int dir = blockIdx.z & 1;
    int b   = blockIdx.z >> 1;
    const float*  qraw   = dir ? q2      : q1;
    const float4* tp     = dir ? g_prepA : g_prepB;
    unsigned*     encOut = dir ? g_enc2  : g_enc1;

    int q0 = b * NPTS + blockIdx.x * QB;

    __shared__ float4 sh[MC];   // 8 KB: 256 target-pairs * 2 float4

    const float4* gsrc = tp + b * NPTS + blockIdx.y * MC;
    for (int i = threadIdx.x; i < MC; i += TPB) sh[i] = gsrc[i];

    unsigned long long X2[TQ], Y2[TQ], Z2[TQ];
    float mnlo[TQ], mnhi[TQ];
#pragma unroll
    for (int k = 0; k < TQ; k++) {
        int qg = q0 + threadIdx.x + k * TPB;
        float x = qraw[3*qg], y = qraw[3*qg+1], z = qraw[3*qg+2];
        X2[k] = pk2(x, x); Y2[k] = pk2(y, y); Z2[k] = pk2(z, z);
        mnlo[k] = __int_as_float(0x7f800000);   // +inf
        mnhi[k] = __int_as_float(0x7f800000);
    }
    __syncthreads();

#pragma unroll 2
    for (int p = 0; p < MC / 2; ++p) {
        float4 A  = sh[2*p];
        float4 Bv = sh[2*p + 1];
        unsigned long long NX = pk2(A.x,  A.y);
        unsigned long long NY = pk2(A.z,  A.w);
        unsigned long long NZ = pk2(Bv.x, Bv.y);
        unsigned long long H  = pk2(Bv.z, Bv.w);
#pragma unroll
        for (int k = 0; k < TQ; k++) {
            float lo, hi;
            // e = h - (xq*xt + yq*yt + zq*zt), two targets per packed op
            asm("{\n\t.reg .b64 t;\n\t"
                "fma.rn.f32x2 t, %2, %3, %4;\n\t"
                "fma.rn.f32x2 t, %5, %6, t;\n\t"
                "fma.rn.f32x2 t, %7, %8, t;\n\t"
                "mov.b64 {%0,%1}, t;\n\t}"
                : "=f"(lo), "=f"(hi)
                : "l"(Z2[k]), "l"(NZ), "l"(H),
                  "l"(Y2[k]), "l"(NY),
                  "l"(X2[k]), "l"(NX));
            mnlo[k] = fminf(mnlo[k], lo);   // alu pipe, independent chains
            mnhi[k] = fminf(mnhi[k], hi);
        }
    }

#pragma unroll
    for (int k = 0; k < TQ; k++)
        atomicMin(&encOut[q0 + threadIdx.x + k * TPB],
                  fenc(fminf(mnlo[k], mnhi[k])));
}

// Deterministic two-stage reduction: dist = a^2 + 2*e_min ; output = (sum1+sum2)/(B*N)
__global__ void reduce1_kernel(const float* __restrict__ a1, const float* __restrict__ a2r) {
    __shared__ float ss[256];
    int blk = blockIdx.x;                       // 0..127
    const float*    raw = (blk & 64) ? a2r    : a1;
    const unsigned* enc = (blk & 64) ? g_enc2 : g_enc1;
    int base = (blk & 63) * 512;
    float s = 0.f;
    for (int i = threadIdx.x; i < 512; i += 256) {
        int idx = base + i;
        float x = raw[3*idx], y = raw[3*idx+1], z = raw[3*idx+2];
        s += (x*x + y*y + z*z) + 2.0f * fdec(enc[idx]);
    }
    ss[threadIdx.x] = s; __syncthreads();
    for (int o = 128; o > 0; o >>= 1) {
        if (threadIdx.x < o) ss[threadIdx.x] += ss[threadIdx.x + o];
        __syncthreads();
    }
    if (threadIdx.x == 0) g_part[blk] = ss[0];
}

__global__ void reduce2_kernel(float* __restrict__ out) {
    __shared__ float ss[128];
    ss[threadIdx.x] = g_part[threadIdx.x]; __syncthreads();
    for (int o = 64; o > 0; o >>= 1) {
        if (threadIdx.x < o) ss[threadIdx.x] += ss[threadIdx.x + o];
        __syncthreads();
    }
    if (threadIdx.x == 0) out[0] = ss[0] * (1.0f / (float)(NB * NPTS));
}

extern "C" void kernel_launch(void* const* d_in, const int* in_sizes, int n_in,
                              void* d_out, int out_size) {
    const float* a1 = (const float*)d_in[0];   // array1 [4,8192,3]
    const float* a2 = (const float*)d_in[1];   // array2 [4,8192,3]
    float* out = (float*)d_out;

    prep_kernel<<<NPAIRS / 256, 256>>>(a1, 0);  // -> g_prepA + init g_enc1
    prep_kernel<<<NPAIRS / 256, 256>>>(a2, 1);  // -> g_prepB + init g_enc2

    dim3 grid(NPTS / QB, NPTS / MC, 2 * NB);    // (16, 16, 8) = 2048 blocks
    pass_kernel<<<grid, TPB>>>(a1, a2);         // both directions fused

    reduce1_kernel<<<128, 256>>>(a1, a2);
    reduce2_kernel<<<1, 128>>>(out);
}